// round 1
// baseline (speedup 1.0000x reference)
#include <cuda_runtime.h>
#include <cstdint>
#include <cstddef>

// ---------------- problem constants ----------------
#define S_LEN   4096
#define D_DIM   2048
#define C_DIM   64
#define M_CH    4
#define NC_CH   1024
#define TOPK_N  512
#define NH_N    16
#define DC_N    512
#define NHI_N   4
#define CI_N    64
#define NG_N    4
#define DG_N    512

#define NEG_INF (__int_as_float(0xff800000))

// ---------------- scratch (device globals; no allocation allowed) -------
__device__ float g_ca[S_LEN * C_DIM];
__device__ float g_cb[S_LEN * C_DIM];
__device__ float g_za[S_LEN * C_DIM];
__device__ float g_zb[S_LEN * C_DIM];
__device__ float g_kc[NC_CH * C_DIM];
__device__ float g_cq[S_LEN * DC_N];
__device__ float g_qi[S_LEN * NHI_N * CI_N];
__device__ float g_hw[S_LEN * NHI_N];
__device__ float g_ko[NC_CH * D_DIM];
__device__ float g_kp[NC_CH * CI_N];
__device__ float g_qf[S_LEN * NH_N * C_DIM];
__device__ float g_is[(size_t)S_LEN * NC_CH];
__device__ int   g_ti[S_LEN * TOPK_N];
__device__ float g_ao[S_LEN * NH_N * C_DIM];
__device__ float g_gb[(size_t)S_LEN * NG_N * DG_N];

// ---------------- generic fp32 SGEMM: C = A(MxK) @ B(KxN), row-major ----
// 128x128 block tile, BK=8, 256 threads, 8x8 per-thread register tile.
// Requires K % 8 == 0 (true for all call sites), arbitrary M/N with guards.
__global__ __launch_bounds__(256) void sgemm_kernel(
    const float* __restrict__ A, const float* __restrict__ B,
    float* __restrict__ Cc, int M, int N, int K, int lda, int ldb, int ldc) {
  __shared__ float As[8][128];
  __shared__ float Bs[8][132];
  const int bm = blockIdx.y * 128;
  const int bn = blockIdx.x * 128;
  const int tid = threadIdx.x;
  const int tx = tid & 15, ty = tid >> 4;
  const int arow = tid >> 1, acol = (tid & 1) * 4;   // A tile: 128 rows x 8 k
  const int brow = tid >> 5, bcol = (tid & 31) * 4;  // B tile: 8 k x 128 cols

  float acc[8][8];
#pragma unroll
  for (int i = 0; i < 8; i++)
#pragma unroll
    for (int j = 0; j < 8; j++) acc[i][j] = 0.f;

  for (int k0 = 0; k0 < K; k0 += 8) {
    float4 av = make_float4(0.f, 0.f, 0.f, 0.f);
    if (bm + arow < M)
      av = *reinterpret_cast<const float4*>(A + (size_t)(bm + arow) * lda + k0 + acol);
    As[acol + 0][arow] = av.x;
    As[acol + 1][arow] = av.y;
    As[acol + 2][arow] = av.z;
    As[acol + 3][arow] = av.w;

    float4 bv;
    const float* Brow = B + (size_t)(k0 + brow) * ldb + bn + bcol;
    if (bn + bcol + 3 < N) {
      bv = *reinterpret_cast<const float4*>(Brow);
    } else {
      bv.x = (bn + bcol + 0 < N) ? Brow[0] : 0.f;
      bv.y = (bn + bcol + 1 < N) ? Brow[1] : 0.f;
      bv.z = (bn + bcol + 2 < N) ? Brow[2] : 0.f;
      bv.w = 0.f;
    }
    Bs[brow][bcol + 0] = bv.x;
    Bs[brow][bcol + 1] = bv.y;
    Bs[brow][bcol + 2] = bv.z;
    Bs[brow][bcol + 3] = bv.w;
    __syncthreads();

#pragma unroll
    for (int kk = 0; kk < 8; kk++) {
      float a[8], b[8];
#pragma unroll
      for (int i = 0; i < 8; i++) a[i] = As[kk][ty * 8 + i];
#pragma unroll
      for (int j = 0; j < 8; j++) b[j] = Bs[kk][tx * 8 + j];
#pragma unroll
      for (int i = 0; i < 8; i++)
#pragma unroll
        for (int j = 0; j < 8; j++) acc[i][j] += a[i] * b[j];
    }
    __syncthreads();
  }

#pragma unroll
  for (int i = 0; i < 8; i++) {
    int r = bm + ty * 8 + i;
    if (r >= M) continue;
#pragma unroll
    for (int j = 0; j < 8; j++) {
      int cc = bn + tx * 8 + j;
      if (cc < N) Cc[(size_t)r * ldc + cc] = acc[i][j];
    }
  }
}

// ---------------- k_orig = mean over the M=4 tokens of each chunk -------
__global__ void kmean_kernel(const float* __restrict__ x) {
  int idx = blockIdx.x * 256 + threadIdx.x;
  if (idx >= NC_CH * D_DIM) return;
  int nc = idx / D_DIM, d = idx - nc * D_DIM;
  const float* p = x + (size_t)nc * 4 * D_DIM + d;
  g_ko[idx] = 0.25f * (p[0] + p[D_DIM] + p[2 * D_DIM] + p[3 * D_DIM]);
}

// ------------- compression softmax (over 8 candidates) + LayerNorm ------
__global__ void compress_kernel(const float* __restrict__ b_a,
                                const float* __restrict__ b_b,
                                const float* __restrict__ kvn_w,
                                const float* __restrict__ kvn_b) {
  int nc = blockIdx.x;
  int c = threadIdx.x;  // 64
  float lg[8], val[8];
#pragma unroll
  for (int m = 0; m < 4; m++) {
    int cur = (nc * 4 + m) * 64 + c;
    lg[4 + m] = g_za[cur] + b_a[m * 64 + c];
    val[4 + m] = g_ca[cur];
    if (nc > 0) {
      int prev = ((nc - 1) * 4 + m) * 64 + c;
      lg[m] = g_zb[prev] + b_b[m * 64 + c];
      val[m] = g_cb[prev];
    } else {
      lg[m] = -1e30f + b_b[m * 64 + c];
      val[m] = 0.f;
    }
  }
  float mx = lg[0];
#pragma unroll
  for (int i = 1; i < 8; i++) mx = fmaxf(mx, lg[i]);
  float se = 0.f, comp = 0.f;
#pragma unroll
  for (int i = 0; i < 8; i++) {
    float e = expf(lg[i] - mx);
    se += e;
    comp += e * val[i];
  }
  comp /= se;

  __shared__ float red[64];
  red[c] = comp;
  __syncthreads();
  for (int off = 32; off > 0; off >>= 1) {
    if (c < off) red[c] += red[c + off];
    __syncthreads();
  }
  float mu = red[0] * (1.f / 64.f);
  __syncthreads();
  float dv = comp - mu;
  red[c] = dv * dv;
  __syncthreads();
  for (int off = 32; off > 0; off >>= 1) {
    if (c < off) red[c] += red[c + off];
    __syncthreads();
  }
  float var = red[0] * (1.f / 64.f);
  g_kc[nc * 64 + c] = dv * rsqrtf(var + 1e-6f) * kvn_w[c] + kvn_b[c];
}

// ------------- per-(s,h) LayerNorm then RoPE on last 32 channels --------
__global__ void qln_rope_kernel(const float* __restrict__ qn_w,
                                const float* __restrict__ qn_b) {
  int s = blockIdx.x;
  int c = threadIdx.x;  // 64
  int h = threadIdx.y;  // 16
  float v = g_qf[(size_t)s * 1024 + h * 64 + c];
  __shared__ float red[16][64];
  __shared__ float lnb[16][65];
  red[h][c] = v;
  __syncthreads();
  for (int off = 32; off > 0; off >>= 1) {
    if (c < off) red[h][c] += red[h][c + off];
    __syncthreads();
  }
  float mu = red[h][0] * (1.f / 64.f);
  __syncthreads();
  float dv = v - mu;
  red[h][c] = dv * dv;
  __syncthreads();
  for (int off = 32; off > 0; off >>= 1) {
    if (c < off) red[h][c] += red[h][c + off];
    __syncthreads();
  }
  float var = red[h][0] * (1.f / 64.f);
  float ln = dv * rsqrtf(var + 1e-6f) * qn_w[c] + qn_b[c];
  lnb[h][c] = ln;
  __syncthreads();
  float outv;
  if (c < 32) {
    outv = ln;
  } else {
    int j = (c - 32) >> 1;
    float inv = powf(10000.f, -(float)j / 16.f);
    float ang = (float)s * inv;
    float cs = cosf(ang), sn = sinf(ang);
    float x0 = lnb[h][32 + 2 * j], x1 = lnb[h][32 + 2 * j + 1];
    outv = ((c & 1) == 0) ? (x0 * cs - x1 * sn) : (x0 * sn + x1 * cs);
  }
  g_qf[(size_t)s * 1024 + h * 64 + c] = outv;
}

// ------------- indexer scores: relu(q_i . k_proj) weighted by hw --------
__global__ void iscore_kernel() {
  int s = blockIdx.x;
  __shared__ float qs[256];
  __shared__ float ws[4];
  int tid = threadIdx.x;  // 256
  qs[tid] = g_qi[(size_t)s * 256 + tid];
  if (tid < 4) ws[tid] = g_hw[s * 4 + tid];
  __syncthreads();
  for (int k = tid; k < NC_CH; k += 256) {
    const float* kr = g_kp + k * 64;
    float d0 = 0.f, d1 = 0.f, d2 = 0.f, d3 = 0.f;
#pragma unroll
    for (int c = 0; c < 64; c++) {
      float kv = kr[c];
      d0 += qs[c] * kv;
      d1 += qs[64 + c] * kv;
      d2 += qs[128 + c] * kv;
      d3 += qs[192 + c] * kv;
    }
    float sc = fmaxf(d0, 0.f) * ws[0] + fmaxf(d1, 0.f) * ws[1] +
               fmaxf(d2, 0.f) * ws[2] + fmaxf(d3, 0.f) * ws[3];
    g_is[(size_t)s * NC_CH + k] = (k < s) ? sc : NEG_INF;
  }
}

// ------------- exact top-512: bitonic sort by (value desc, index asc) ---
// Matches jax.lax.top_k tie-breaking (lowest index first among equals),
// which matters because selected -inf chunks still get real attn scores.
__global__ __launch_bounds__(512) void topk_kernel() {
  int s = blockIdx.x, tid = threadIdx.x;  // 512
  __shared__ float v[1024];
  __shared__ int ix[1024];
  v[tid] = g_is[(size_t)s * 1024 + tid];
  ix[tid] = tid;
  v[tid + 512] = g_is[(size_t)s * 1024 + tid + 512];
  ix[tid + 512] = tid + 512;
  __syncthreads();
  for (int k = 2; k <= 1024; k <<= 1) {
    for (int j = k >> 1; j > 0; j >>= 1) {
      for (int t = tid; t < 1024; t += 512) {
        int p = t ^ j;
        if (p > t) {
          float va = v[t], vb = v[p];
          int ia = ix[t], ib = ix[p];
          bool before = (va > vb) || (va == vb && ia < ib);
          bool dir = ((t & k) == 0);
          if (before != dir) {
            v[t] = vb; v[p] = va;
            ix[t] = ib; ix[p] = ia;
          }
        }
      }
      __syncthreads();
    }
  }
  g_ti[(size_t)s * 512 + tid] = ix[tid];
}

// ------------- gathered sparse attention with sink denominator ----------
__global__ __launch_bounds__(256) void attn_kernel(const float* __restrict__ sink) {
  int s = blockIdx.x, tid = threadIdx.x;  // 256
  __shared__ float qs[1024];
  __shared__ float ew[16 * 512];
  __shared__ int idxs[512];
  __shared__ float denom[16];
  __shared__ float part[256];
#pragma unroll
  for (int i = 0; i < 4; i++) qs[tid + 256 * i] = g_qf[(size_t)s * 1024 + tid + 256 * i];
  idxs[tid] = g_ti[(size_t)s * 512 + tid];
  idxs[tid + 256] = g_ti[(size_t)s * 512 + tid + 256];
  __syncthreads();

  // phase 1: e = exp(score) with mask (reference has NO max-subtraction)
  for (int k = tid; k < 512; k += 256) {
    int ck = idxs[k];
    const float4* kr = reinterpret_cast<const float4*>(g_kc + ck * 64);
    float d[16];
#pragma unroll
    for (int h = 0; h < 16; h++) d[h] = 0.f;
#pragma unroll
    for (int c4 = 0; c4 < 16; c4++) {
      float4 kv = kr[c4];
#pragma unroll
      for (int h = 0; h < 16; h++) {
        d[h] += qs[h * 64 + c4 * 4 + 0] * kv.x + qs[h * 64 + c4 * 4 + 1] * kv.y +
                qs[h * 64 + c4 * 4 + 2] * kv.z + qs[h * 64 + c4 * 4 + 3] * kv.w;
      }
    }
    bool valid = (s < ck * 4);
#pragma unroll
    for (int h = 0; h < 16; h++) ew[h * 512 + k] = valid ? expf(d[h] * 0.125f) : 0.f;
  }
  __syncthreads();

  // phase 2: per-head denominator (+ sink term)
  {
    int h = tid >> 4, seg = tid & 15;
    float p = 0.f;
    int base = h * 512 + seg * 32;
#pragma unroll
    for (int k = 0; k < 32; k++) p += ew[base + k];
    part[tid] = p;
    __syncthreads();
    if (seg < 8) part[tid] += part[tid + 8];
    __syncthreads();
    if (seg < 4) part[tid] += part[tid + 4];
    __syncthreads();
    if (seg < 2) part[tid] += part[tid + 2];
    __syncthreads();
    if (seg == 0) denom[h] = part[tid] + part[tid + 1] + expf(sink[h]);
    __syncthreads();
  }

  // phase 3: out[h][c] = sum_k e[h][k] * kc[idx[k]][c] / denom[h]
  int c = tid & 63, g = tid >> 6;  // 4 head-groups of 4
  float acc0 = 0.f, acc1 = 0.f, acc2 = 0.f, acc3 = 0.f;
  for (int k = 0; k < 512; k++) {
    int ck = idxs[k];
    float kv = g_kc[ck * 64 + c];
    acc0 += ew[(g) * 512 + k] * kv;
    acc1 += ew[(g + 4) * 512 + k] * kv;
    acc2 += ew[(g + 8) * 512 + k] * kv;
    acc3 += ew[(g + 12) * 512 + k] * kv;
  }
  g_ao[(size_t)s * 1024 + (g) * 64 + c] = acc0 / denom[g];
  g_ao[(size_t)s * 1024 + (g + 4) * 64 + c] = acc1 / denom[g + 4];
  g_ao[(size_t)s * 1024 + (g + 8) * 64 + c] = acc2 / denom[g + 8];
  g_ao[(size_t)s * 1024 + (g + 12) * 64 + c] = acc3 / denom[g + 12];
}

// ---------------------------- launcher ----------------------------------
extern "C" void kernel_launch(void* const* d_in, const int* in_sizes, int n_in,
                              void* d_out, int out_size) {
  (void)in_sizes; (void)n_in; (void)out_size;
  const float* x      = (const float*)d_in[0];
  const float* w_kva  = (const float*)d_in[1];
  const float* w_kvb  = (const float*)d_in[2];
  const float* w_za   = (const float*)d_in[3];
  const float* w_zb   = (const float*)d_in[4];
  const float* b_a    = (const float*)d_in[5];
  const float* b_b    = (const float*)d_in[6];
  const float* w_dq   = (const float*)d_in[7];
  const float* w_iuq  = (const float*)d_in[8];
  const float* w_w    = (const float*)d_in[9];
  const float* w_k    = (const float*)d_in[10];
  const float* w_uq   = (const float*)d_in[11];
  const float* o_down = (const float*)d_in[12];
  const float* o_up   = (const float*)d_in[13];
  const float* kvn_w  = (const float*)d_in[14];
  const float* kvn_b  = (const float*)d_in[15];
  const float* qn_w   = (const float*)d_in[16];
  const float* qn_b   = (const float*)d_in[17];
  const float* sink   = (const float*)d_in[18];
  float* out = (float*)d_out;

  void *p_ca, *p_cb, *p_za, *p_zb, *p_cq, *p_qi, *p_hw, *p_ko, *p_kp, *p_qf, *p_ao, *p_gb;
  cudaGetSymbolAddress(&p_ca, g_ca);
  cudaGetSymbolAddress(&p_cb, g_cb);
  cudaGetSymbolAddress(&p_za, g_za);
  cudaGetSymbolAddress(&p_zb, g_zb);
  cudaGetSymbolAddress(&p_cq, g_cq);
  cudaGetSymbolAddress(&p_qi, g_qi);
  cudaGetSymbolAddress(&p_hw, g_hw);
  cudaGetSymbolAddress(&p_ko, g_ko);
  cudaGetSymbolAddress(&p_kp, g_kp);
  cudaGetSymbolAddress(&p_qf, g_qf);
  cudaGetSymbolAddress(&p_ao, g_ao);
  cudaGetSymbolAddress(&p_gb, g_gb);

  auto grid2 = [](int M, int N) { return dim3((unsigned)((N + 127) / 128), (unsigned)((M + 127) / 128)); };

  // stage A: linear projections
  sgemm_kernel<<<grid2(S_LEN, C_DIM), 256>>>(x, w_kva, (float*)p_ca, S_LEN, C_DIM, D_DIM, D_DIM, C_DIM, C_DIM);
  sgemm_kernel<<<grid2(S_LEN, C_DIM), 256>>>(x, w_kvb, (float*)p_cb, S_LEN, C_DIM, D_DIM, D_DIM, C_DIM, C_DIM);
  sgemm_kernel<<<grid2(S_LEN, C_DIM), 256>>>(x, w_za, (float*)p_za, S_LEN, C_DIM, D_DIM, D_DIM, C_DIM, C_DIM);
  sgemm_kernel<<<grid2(S_LEN, C_DIM), 256>>>(x, w_zb, (float*)p_zb, S_LEN, C_DIM, D_DIM, D_DIM, C_DIM, C_DIM);
  sgemm_kernel<<<grid2(S_LEN, DC_N), 256>>>(x, w_dq, (float*)p_cq, S_LEN, DC_N, D_DIM, D_DIM, DC_N, DC_N);
  sgemm_kernel<<<grid2(S_LEN, 4), 256>>>(x, w_w, (float*)p_hw, S_LEN, 4, D_DIM, D_DIM, 4, 4);

  // stage B: chunk compression + LN(kc)
  compress_kernel<<<NC_CH, 64>>>(b_a, b_b, kvn_w, kvn_b);

  // stage C: indexer path
  sgemm_kernel<<<grid2(S_LEN, NHI_N * CI_N), 256>>>((const float*)p_cq, w_iuq, (float*)p_qi,
                                                    S_LEN, NHI_N * CI_N, DC_N, DC_N, NHI_N * CI_N, NHI_N * CI_N);
  kmean_kernel<<<(NC_CH * D_DIM + 255) / 256, 256>>>(x);
  sgemm_kernel<<<grid2(NC_CH, CI_N), 256>>>((const float*)p_ko, w_k, (float*)p_kp, NC_CH, CI_N, D_DIM, D_DIM, CI_N, CI_N);
  iscore_kernel<<<S_LEN, 256>>>();
  topk_kernel<<<S_LEN, 512>>>();

  // stage D: q path (LN + rope in-place)
  sgemm_kernel<<<grid2(S_LEN, NH_N * C_DIM), 256>>>((const float*)p_cq, w_uq, (float*)p_qf,
                                                    S_LEN, NH_N * C_DIM, DC_N, DC_N, NH_N * C_DIM, NH_N * C_DIM);
  qln_rope_kernel<<<S_LEN, dim3(64, 16)>>>(qn_w, qn_b);

  // stage E: sparse attention over top-k compressed chunks
  attn_kernel<<<S_LEN, 256>>>(sink);

  // stage F: grouped o_down then o_up
  for (int g = 0; g < NG_N; g++) {
    sgemm_kernel<<<grid2(S_LEN, DG_N), 256>>>((const float*)p_ao + g * 256,
                                              o_down + (size_t)g * 256 * DG_N,
                                              (float*)p_gb + g * DG_N,
                                              S_LEN, DG_N, 256, NH_N * C_DIM, DG_N, NG_N * DG_N);
  }
  sgemm_kernel<<<grid2(S_LEN, D_DIM), 256>>>((const float*)p_gb, o_up, out,
                                             S_LEN, D_DIM, NG_N * DG_N, NG_N * DG_N, D_DIM, D_DIM);
}

// round 2
// speedup vs baseline: 1.4705x; 1.4705x over previous
#include <cuda_runtime.h>
#include <cstdint>
#include <cstddef>

// ---------------- problem constants ----------------
#define S_LEN   4096
#define D_DIM   2048
#define C_DIM   64
#define M_CH    4
#define NC_CH   1024
#define TOPK_N  512
#define NH_N    16
#define DC_N    512
#define NHI_N   4
#define CI_N    64
#define NG_N    4
#define DG_N    512

#define NEG_INF (__int_as_float(0xff800000))

// ---------------- scratch (device globals; no allocation allowed) -------
__device__ float g_ca[S_LEN * C_DIM];
__device__ float g_cb[S_LEN * C_DIM];
__device__ float g_za[S_LEN * C_DIM];
__device__ float g_zb[S_LEN * C_DIM];
__device__ float g_kc[NC_CH * C_DIM];
__device__ float g_cq[S_LEN * DC_N];
__device__ float g_qi[S_LEN * NHI_N * CI_N];
__device__ float g_hw[S_LEN * NHI_N];
__device__ float g_ko[NC_CH * D_DIM];
__device__ float g_kp[NC_CH * CI_N];
__device__ float g_qf[S_LEN * NH_N * C_DIM];
__device__ float g_is[(size_t)S_LEN * NC_CH];
__device__ int   g_ti[S_LEN * TOPK_N];
__device__ float g_ao[S_LEN * NH_N * C_DIM];
__device__ float g_gb[(size_t)S_LEN * NG_N * DG_N];

// ========== generic fp32 SGEMM (fast path: M%128==0, N%128==0, K%8==0) ==
// 128x128 block tile, BK=8, 256 threads, 8x8 per-thread register tile,
// register-prefetch double buffering, 2 CTAs/SM.
__global__ __launch_bounds__(256, 2) void sgemm_kernel(
    const float* __restrict__ A, const float* __restrict__ B,
    float* __restrict__ Cc, int K, int lda, int ldb, int ldc) {
  __shared__ float As[8][128];
  __shared__ float Bs[8][132];
  const int bm = blockIdx.y * 128;
  const int bn = blockIdx.x * 128;
  const int tid = threadIdx.x;
  const int tx = tid & 15, ty = tid >> 4;
  const int arow = tid >> 1, acol = (tid & 1) * 4;   // A tile: 128 rows x 8 k
  const int brow = tid >> 5, bcol = (tid & 31) * 4;  // B tile: 8 k x 128 cols

  const float* Aptr = A + (size_t)(bm + arow) * lda + acol;
  const float* Bptr = B + (size_t)brow * ldb + bn + bcol;

  float acc[8][8];
#pragma unroll
  for (int i = 0; i < 8; i++)
#pragma unroll
    for (int j = 0; j < 8; j++) acc[i][j] = 0.f;

  float4 av = *reinterpret_cast<const float4*>(Aptr);
  float4 bv = *reinterpret_cast<const float4*>(Bptr);

  for (int k0 = 0; k0 < K; k0 += 8) {
    As[acol + 0][arow] = av.x;
    As[acol + 1][arow] = av.y;
    As[acol + 2][arow] = av.z;
    As[acol + 3][arow] = av.w;
    Bs[brow][bcol + 0] = bv.x;
    Bs[brow][bcol + 1] = bv.y;
    Bs[brow][bcol + 2] = bv.z;
    Bs[brow][bcol + 3] = bv.w;
    __syncthreads();

    if (k0 + 8 < K) {  // prefetch next K-slab while computing this one
      av = *reinterpret_cast<const float4*>(Aptr + k0 + 8);
      bv = *reinterpret_cast<const float4*>(Bptr + (size_t)(k0 + 8) * ldb);
    }

#pragma unroll
    for (int kk = 0; kk < 8; kk++) {
      float a[8], b[8];
#pragma unroll
      for (int i = 0; i < 8; i++) a[i] = As[kk][ty * 8 + i];
#pragma unroll
      for (int j = 0; j < 8; j++) b[j] = Bs[kk][tx * 8 + j];
#pragma unroll
      for (int i = 0; i < 8; i++)
#pragma unroll
        for (int j = 0; j < 8; j++) acc[i][j] += a[i] * b[j];
    }
    __syncthreads();
  }

#pragma unroll
  for (int i = 0; i < 8; i++) {
    float* crow = Cc + (size_t)(bm + ty * 8 + i) * ldc + bn + tx * 8;
    *reinterpret_cast<float4*>(crow) = make_float4(acc[i][0], acc[i][1], acc[i][2], acc[i][3]);
    *reinterpret_cast<float4*>(crow + 4) = make_float4(acc[i][4], acc[i][5], acc[i][6], acc[i][7]);
  }
}

// ========== fused narrow projections: 5 independent (A @ B[2048x64]) ====
// blockIdx.x selects matrix, blockIdx.y the 128-row tile. 128x64 tiles,
// 256 threads, 8x4 micro-tile, register-prefetch.
struct ProjArgs {
  const float* A[5];
  const float* B[5];
  float* Cc[5];
  int M[5];
};

__global__ __launch_bounds__(256, 2) void proj64_kernel(ProjArgs pa) {
  const int mat = blockIdx.x;
  const int bm = blockIdx.y * 128;
  if (bm >= pa.M[mat]) return;  // uniform per block
  const float* A = pa.A[mat];
  const float* B = pa.B[mat];
  float* Cc = pa.Cc[mat];

  __shared__ float As[8][128];
  __shared__ float Bs[8][68];
  const int tid = threadIdx.x;
  const int tx = tid & 15, ty = tid >> 4;          // 16x16 -> 4 cols, 8 rows each
  const int arow = tid >> 1, acol = (tid & 1) * 4;
  const int brow = tid >> 4, bcol = (tid & 15) * 4;  // first 128 threads
  const bool bload = (tid < 128);

  const float* Aptr = A + (size_t)(bm + arow) * D_DIM + acol;
  const float* Bptr = B + (size_t)brow * C_DIM + bcol;

  float acc[8][4];
#pragma unroll
  for (int i = 0; i < 8; i++)
#pragma unroll
    for (int j = 0; j < 4; j++) acc[i][j] = 0.f;

  float4 av = *reinterpret_cast<const float4*>(Aptr);
  float4 bv = bload ? *reinterpret_cast<const float4*>(Bptr) : make_float4(0, 0, 0, 0);

  for (int k0 = 0; k0 < D_DIM; k0 += 8) {
    As[acol + 0][arow] = av.x;
    As[acol + 1][arow] = av.y;
    As[acol + 2][arow] = av.z;
    As[acol + 3][arow] = av.w;
    if (bload) {
      Bs[brow][bcol + 0] = bv.x;
      Bs[brow][bcol + 1] = bv.y;
      Bs[brow][bcol + 2] = bv.z;
      Bs[brow][bcol + 3] = bv.w;
    }
    __syncthreads();

    if (k0 + 8 < D_DIM) {
      av = *reinterpret_cast<const float4*>(Aptr + k0 + 8);
      if (bload) bv = *reinterpret_cast<const float4*>(Bptr + (size_t)(k0 + 8) * C_DIM);
    }

#pragma unroll
    for (int kk = 0; kk < 8; kk++) {
      float a[8], b[4];
#pragma unroll
      for (int i = 0; i < 8; i++) a[i] = As[kk][ty * 8 + i];
#pragma unroll
      for (int j = 0; j < 4; j++) b[j] = Bs[kk][tx * 4 + j];
#pragma unroll
      for (int i = 0; i < 8; i++)
#pragma unroll
        for (int j = 0; j < 4; j++) acc[i][j] += a[i] * b[j];
    }
    __syncthreads();
  }

#pragma unroll
  for (int i = 0; i < 8; i++) {
    float* crow = Cc + (size_t)(bm + ty * 8 + i) * C_DIM + tx * 4;
    *reinterpret_cast<float4*>(crow) = make_float4(acc[i][0], acc[i][1], acc[i][2], acc[i][3]);
  }
}

// ========== hw = x @ w_w [2048x4]: one warp per row, memory-bound ======
__global__ void hw_kernel(const float* __restrict__ x, const float* __restrict__ w_w) {
  int warp = (blockIdx.x * blockDim.x + threadIdx.x) >> 5;
  int lane = threadIdx.x & 31;
  if (warp >= S_LEN) return;
  const float4* xr = reinterpret_cast<const float4*>(x + (size_t)warp * D_DIM);
  const float4* wr = reinterpret_cast<const float4*>(w_w);
  float d0 = 0.f, d1 = 0.f, d2 = 0.f, d3 = 0.f;
  for (int i = lane; i < D_DIM / 4; i += 32) {
    float4 xv = xr[i];
    float4 w0 = wr[i * 4 + 0];
    float4 w1 = wr[i * 4 + 1];
    float4 w2 = wr[i * 4 + 2];
    float4 w3 = wr[i * 4 + 3];
    d0 += xv.x * w0.x + xv.y * w1.x + xv.z * w2.x + xv.w * w3.x;
    d1 += xv.x * w0.y + xv.y * w1.y + xv.z * w2.y + xv.w * w3.y;
    d2 += xv.x * w0.z + xv.y * w1.z + xv.z * w2.z + xv.w * w3.z;
    d3 += xv.x * w0.w + xv.y * w1.w + xv.z * w2.w + xv.w * w3.w;
  }
#pragma unroll
  for (int off = 16; off > 0; off >>= 1) {
    d0 += __shfl_down_sync(0xffffffffu, d0, off);
    d1 += __shfl_down_sync(0xffffffffu, d1, off);
    d2 += __shfl_down_sync(0xffffffffu, d2, off);
    d3 += __shfl_down_sync(0xffffffffu, d3, off);
  }
  if (lane == 0) {
    g_hw[warp * 4 + 0] = d0;
    g_hw[warp * 4 + 1] = d1;
    g_hw[warp * 4 + 2] = d2;
    g_hw[warp * 4 + 3] = d3;
  }
}

// ---------------- k_orig = mean over the M=4 tokens of each chunk -------
__global__ void kmean_kernel(const float* __restrict__ x) {
  int idx = blockIdx.x * 256 + threadIdx.x;
  if (idx >= NC_CH * D_DIM) return;
  int nc = idx / D_DIM, d = idx - nc * D_DIM;
  const float* p = x + (size_t)nc * 4 * D_DIM + d;
  g_ko[idx] = 0.25f * (p[0] + p[D_DIM] + p[2 * D_DIM] + p[3 * D_DIM]);
}

// ------------- compression softmax (over 8 candidates) + LayerNorm ------
__global__ void compress_kernel(const float* __restrict__ b_a,
                                const float* __restrict__ b_b,
                                const float* __restrict__ kvn_w,
                                const float* __restrict__ kvn_b) {
  int nc = blockIdx.x;
  int c = threadIdx.x;  // 64
  float lg[8], val[8];
#pragma unroll
  for (int m = 0; m < 4; m++) {
    int cur = (nc * 4 + m) * 64 + c;
    lg[4 + m] = g_za[cur] + b_a[m * 64 + c];
    val[4 + m] = g_ca[cur];
    if (nc > 0) {
      int prev = ((nc - 1) * 4 + m) * 64 + c;
      lg[m] = g_zb[prev] + b_b[m * 64 + c];
      val[m] = g_cb[prev];
    } else {
      lg[m] = -1e30f + b_b[m * 64 + c];
      val[m] = 0.f;
    }
  }
  float mx = lg[0];
#pragma unroll
  for (int i = 1; i < 8; i++) mx = fmaxf(mx, lg[i]);
  float se = 0.f, comp = 0.f;
#pragma unroll
  for (int i = 0; i < 8; i++) {
    float e = expf(lg[i] - mx);
    se += e;
    comp += e * val[i];
  }
  comp /= se;

  __shared__ float red[64];
  red[c] = comp;
  __syncthreads();
  for (int off = 32; off > 0; off >>= 1) {
    if (c < off) red[c] += red[c + off];
    __syncthreads();
  }
  float mu = red[0] * (1.f / 64.f);
  __syncthreads();
  float dv = comp - mu;
  red[c] = dv * dv;
  __syncthreads();
  for (int off = 32; off > 0; off >>= 1) {
    if (c < off) red[c] += red[c + off];
    __syncthreads();
  }
  float var = red[0] * (1.f / 64.f);
  g_kc[nc * 64 + c] = dv * rsqrtf(var + 1e-6f) * kvn_w[c] + kvn_b[c];
}

// ------------- per-(s,h) LayerNorm then RoPE on last 32 channels --------
__global__ void qln_rope_kernel(const float* __restrict__ qn_w,
                                const float* __restrict__ qn_b) {
  int s = blockIdx.x;
  int c = threadIdx.x;  // 64
  int h = threadIdx.y;  // 16
  float v = g_qf[(size_t)s * 1024 + h * 64 + c];
  __shared__ float red[16][64];
  __shared__ float lnb[16][65];
  red[h][c] = v;
  __syncthreads();
  for (int off = 32; off > 0; off >>= 1) {
    if (c < off) red[h][c] += red[h][c + off];
    __syncthreads();
  }
  float mu = red[h][0] * (1.f / 64.f);
  __syncthreads();
  float dv = v - mu;
  red[h][c] = dv * dv;
  __syncthreads();
  for (int off = 32; off > 0; off >>= 1) {
    if (c < off) red[h][c] += red[h][c + off];
    __syncthreads();
  }
  float var = red[h][0] * (1.f / 64.f);
  float ln = dv * rsqrtf(var + 1e-6f) * qn_w[c] + qn_b[c];
  lnb[h][c] = ln;
  __syncthreads();
  float outv;
  if (c < 32) {
    outv = ln;
  } else {
    int j = (c - 32) >> 1;
    float inv = powf(10000.f, -(float)j / 16.f);
    float ang = (float)s * inv;
    float cs = cosf(ang), sn = sinf(ang);
    float x0 = lnb[h][32 + 2 * j], x1 = lnb[h][32 + 2 * j + 1];
    outv = ((c & 1) == 0) ? (x0 * cs - x1 * sn) : (x0 * sn + x1 * cs);
  }
  g_qf[(size_t)s * 1024 + h * 64 + c] = outv;
}

// ------------- indexer scores: relu(q_i . k_proj) weighted by hw --------
__global__ void iscore_kernel() {
  int s = blockIdx.x;
  __shared__ float qs[256];
  __shared__ float ws[4];
  int tid = threadIdx.x;  // 256
  qs[tid] = g_qi[(size_t)s * 256 + tid];
  if (tid < 4) ws[tid] = g_hw[s * 4 + tid];
  __syncthreads();
  for (int k = tid; k < NC_CH; k += 256) {
    const float* kr = g_kp + k * 64;
    float d0 = 0.f, d1 = 0.f, d2 = 0.f, d3 = 0.f;
#pragma unroll
    for (int c = 0; c < 64; c++) {
      float kv = kr[c];
      d0 += qs[c] * kv;
      d1 += qs[64 + c] * kv;
      d2 += qs[128 + c] * kv;
      d3 += qs[192 + c] * kv;
    }
    float sc = fmaxf(d0, 0.f) * ws[0] + fmaxf(d1, 0.f) * ws[1] +
               fmaxf(d2, 0.f) * ws[2] + fmaxf(d3, 0.f) * ws[3];
    g_is[(size_t)s * NC_CH + k] = (k < s) ? sc : NEG_INF;
  }
}

// ------------- exact top-512: bitonic sort by (value desc, index asc) ---
__global__ __launch_bounds__(512) void topk_kernel() {
  int s = blockIdx.x, tid = threadIdx.x;  // 512
  __shared__ float v[1024];
  __shared__ int ix[1024];
  v[tid] = g_is[(size_t)s * 1024 + tid];
  ix[tid] = tid;
  v[tid + 512] = g_is[(size_t)s * 1024 + tid + 512];
  ix[tid + 512] = tid + 512;
  __syncthreads();
  for (int k = 2; k <= 1024; k <<= 1) {
    for (int j = k >> 1; j > 0; j >>= 1) {
      for (int t = tid; t < 1024; t += 512) {
        int p = t ^ j;
        if (p > t) {
          float va = v[t], vb = v[p];
          int ia = ix[t], ib = ix[p];
          bool before = (va > vb) || (va == vb && ia < ib);
          bool dir = ((t & k) == 0);
          if (before != dir) {
            v[t] = vb; v[p] = va;
            ix[t] = ib; ix[p] = ia;
          }
        }
      }
      __syncthreads();
    }
  }
  g_ti[(size_t)s * 512 + tid] = ix[tid];
}

// ------------- gathered sparse attention with sink denominator ----------
__global__ __launch_bounds__(256) void attn_kernel(const float* __restrict__ sink) {
  int s = blockIdx.x, tid = threadIdx.x;  // 256
  __shared__ float qs[1024];
  __shared__ float ew[16 * 512];
  __shared__ int idxs[512];
  __shared__ float denom[16];
  __shared__ float part[256];
#pragma unroll
  for (int i = 0; i < 4; i++) qs[tid + 256 * i] = g_qf[(size_t)s * 1024 + tid + 256 * i];
  idxs[tid] = g_ti[(size_t)s * 512 + tid];
  idxs[tid + 256] = g_ti[(size_t)s * 512 + tid + 256];
  __syncthreads();

  for (int k = tid; k < 512; k += 256) {
    int ck = idxs[k];
    const float4* kr = reinterpret_cast<const float4*>(g_kc + ck * 64);
    float d[16];
#pragma unroll
    for (int h = 0; h < 16; h++) d[h] = 0.f;
#pragma unroll
    for (int c4 = 0; c4 < 16; c4++) {
      float4 kv = kr[c4];
#pragma unroll
      for (int h = 0; h < 16; h++) {
        d[h] += qs[h * 64 + c4 * 4 + 0] * kv.x + qs[h * 64 + c4 * 4 + 1] * kv.y +
                qs[h * 64 + c4 * 4 + 2] * kv.z + qs[h * 64 + c4 * 4 + 3] * kv.w;
      }
    }
    bool valid = (s < ck * 4);
#pragma unroll
    for (int h = 0; h < 16; h++) ew[h * 512 + k] = valid ? expf(d[h] * 0.125f) : 0.f;
  }
  __syncthreads();

  {
    int h = tid >> 4, seg = tid & 15;
    float p = 0.f;
    int base = h * 512 + seg * 32;
#pragma unroll
    for (int k = 0; k < 32; k++) p += ew[base + k];
    part[tid] = p;
    __syncthreads();
    if (seg < 8) part[tid] += part[tid + 8];
    __syncthreads();
    if (seg < 4) part[tid] += part[tid + 4];
    __syncthreads();
    if (seg < 2) part[tid] += part[tid + 2];
    __syncthreads();
    if (seg == 0) denom[h] = part[tid] + part[tid + 1] + expf(sink[h]);
    __syncthreads();
  }

  int c = tid & 63, g = tid >> 6;
  float acc0 = 0.f, acc1 = 0.f, acc2 = 0.f, acc3 = 0.f;
  for (int k = 0; k < 512; k++) {
    int ck = idxs[k];
    float kv = g_kc[ck * 64 + c];
    acc0 += ew[(g) * 512 + k] * kv;
    acc1 += ew[(g + 4) * 512 + k] * kv;
    acc2 += ew[(g + 8) * 512 + k] * kv;
    acc3 += ew[(g + 12) * 512 + k] * kv;
  }
  g_ao[(size_t)s * 1024 + (g) * 64 + c] = acc0 / denom[g];
  g_ao[(size_t)s * 1024 + (g + 4) * 64 + c] = acc1 / denom[g + 4];
  g_ao[(size_t)s * 1024 + (g + 8) * 64 + c] = acc2 / denom[g + 8];
  g_ao[(size_t)s * 1024 + (g + 12) * 64 + c] = acc3 / denom[g + 12];
}

// ---------------------------- launcher ----------------------------------
extern "C" void kernel_launch(void* const* d_in, const int* in_sizes, int n_in,
                              void* d_out, int out_size) {
  (void)in_sizes; (void)n_in; (void)out_size;
  const float* x      = (const float*)d_in[0];
  const float* w_kva  = (const float*)d_in[1];
  const float* w_kvb  = (const float*)d_in[2];
  const float* w_za   = (const float*)d_in[3];
  const float* w_zb   = (const float*)d_in[4];
  const float* b_a    = (const float*)d_in[5];
  const float* b_b    = (const float*)d_in[6];
  const float* w_dq   = (const float*)d_in[7];
  const float* w_iuq  = (const float*)d_in[8];
  const float* w_w    = (const float*)d_in[9];
  const float* w_k    = (const float*)d_in[10];
  const float* w_uq   = (const float*)d_in[11];
  const float* o_down = (const float*)d_in[12];
  const float* o_up   = (const float*)d_in[13];
  const float* kvn_w  = (const float*)d_in[14];
  const float* kvn_b  = (const float*)d_in[15];
  const float* qn_w   = (const float*)d_in[16];
  const float* qn_b   = (const float*)d_in[17];
  const float* sink   = (const float*)d_in[18];
  float* out = (float*)d_out;

  void *p_ca, *p_cb, *p_za, *p_zb, *p_cq, *p_qi, *p_ko, *p_kp, *p_qf, *p_ao, *p_gb;
  cudaGetSymbolAddress(&p_ca, g_ca);
  cudaGetSymbolAddress(&p_cb, g_cb);
  cudaGetSymbolAddress(&p_za, g_za);
  cudaGetSymbolAddress(&p_zb, g_zb);
  cudaGetSymbolAddress(&p_cq, g_cq);
  cudaGetSymbolAddress(&p_qi, g_qi);
  cudaGetSymbolAddress(&p_ko, g_ko);
  cudaGetSymbolAddress(&p_kp, g_kp);
  cudaGetSymbolAddress(&p_qf, g_qf);
  cudaGetSymbolAddress(&p_ao, g_ao);
  cudaGetSymbolAddress(&p_gb, g_gb);

  auto grid2 = [](int M, int N) { return dim3((unsigned)(N / 128), (unsigned)(M / 128)); };

  // chunk means first (feeds k_proj inside fused projections)
  kmean_kernel<<<(NC_CH * D_DIM + 255) / 256, 256>>>(x);

  // fused narrow projections: c_a, c_b, z_a, z_b (A = x), k_proj (A = g_ko)
  ProjArgs pa;
  pa.A[0] = x;     pa.B[0] = w_kva; pa.Cc[0] = (float*)p_ca; pa.M[0] = S_LEN;
  pa.A[1] = x;     pa.B[1] = w_kvb; pa.Cc[1] = (float*)p_cb; pa.M[1] = S_LEN;
  pa.A[2] = x;     pa.B[2] = w_za;  pa.Cc[2] = (float*)p_za; pa.M[2] = S_LEN;
  pa.A[3] = x;     pa.B[3] = w_zb;  pa.Cc[3] = (float*)p_zb; pa.M[3] = S_LEN;
  pa.A[4] = (const float*)p_ko; pa.B[4] = w_k; pa.Cc[4] = (float*)p_kp; pa.M[4] = NC_CH;
  proj64_kernel<<<dim3(5, S_LEN / 128), 256>>>(pa);

  // hw = x @ w_w (warp per row)
  hw_kernel<<<S_LEN / 8, 256>>>(x, w_w);

  // c_q = x @ w_dq
  sgemm_kernel<<<grid2(S_LEN, DC_N), 256>>>(x, w_dq, (float*)p_cq, D_DIM, D_DIM, DC_N, DC_N);

  // chunk compression + LN(kc)
  compress_kernel<<<NC_CH, 64>>>(b_a, b_b, kvn_w, kvn_b);

  // indexer path
  sgemm_kernel<<<grid2(S_LEN, NHI_N * CI_N), 256>>>((const float*)p_cq, w_iuq, (float*)p_qi,
                                                    DC_N, DC_N, NHI_N * CI_N, NHI_N * CI_N);
  iscore_kernel<<<S_LEN, 256>>>();
  topk_kernel<<<S_LEN, 512>>>();

  // q path (LN + rope in-place)
  sgemm_kernel<<<grid2(S_LEN, NH_N * C_DIM), 256>>>((const float*)p_cq, w_uq, (float*)p_qf,
                                                    DC_N, DC_N, NH_N * C_DIM, NH_N * C_DIM);
  qln_rope_kernel<<<S_LEN, dim3(64, 16)>>>(qn_w, qn_b);

  // sparse attention over top-k compressed chunks
  attn_kernel<<<S_LEN, 256>>>(sink);

  // grouped o_down then o_up
  for (int g = 0; g < NG_N; g++) {
    sgemm_kernel<<<grid2(S_LEN, DG_N), 256>>>((const float*)p_ao + g * 256,
                                              o_down + (size_t)g * 256 * DG_N,
                                              (float*)p_gb + g * DG_N,
                                              256, NH_N * C_DIM, DG_N, NG_N * DG_N);
  }
  sgemm_kernel<<<grid2(S_LEN, D_DIM), 256>>>((const float*)p_gb, o_up, out,
                                             NG_N * DG_N, NG_N * DG_N, D_DIM, D_DIM);
}

// round 4
// speedup vs baseline: 2.7491x; 1.8695x over previous
#include <cuda_runtime.h>
#include <cstdint>
#include <cstddef>

// ---------------- problem constants ----------------
#define S_LEN   4096
#define D_DIM   2048
#define C_DIM   64
#define M_CH    4
#define NC_CH   1024
#define TOPK_N  512
#define NH_N    16
#define DC_N    512
#define NHI_N   4
#define CI_N    64
#define NG_N    4
#define DG_N    512

#define NEG_INF (__int_as_float(0xff800000))

// ---------------- scratch (device globals; no allocation allowed) -------
__device__ float g_ca[S_LEN * C_DIM];
__device__ float g_cb[S_LEN * C_DIM];
__device__ float g_za[S_LEN * C_DIM];
__device__ float g_zb[S_LEN * C_DIM];
__device__ float g_kc[NC_CH * C_DIM];
__device__ float g_cq[S_LEN * DC_N];
__device__ float g_qi[S_LEN * NHI_N * CI_N];
__device__ float g_hw[S_LEN * NHI_N];
__device__ float g_ko[NC_CH * D_DIM];
__device__ float g_kp[NC_CH * CI_N];
__device__ float g_qf[S_LEN * NH_N * C_DIM];
__device__ float g_is[(size_t)S_LEN * NC_CH];
__device__ int   g_ti[S_LEN * TOPK_N];
__device__ float g_ao[S_LEN * NH_N * C_DIM];
__device__ float g_gb[(size_t)S_LEN * NG_N * DG_N];

// ========== fp32 SGEMM, double-buffered smem, optional batch (blockIdx.z)
__global__ __launch_bounds__(256, 2) void sgemm_kernel(
    const float* __restrict__ A, const float* __restrict__ B,
    float* __restrict__ Cc, int K, int lda, int ldb, int ldc,
    long sA, long sB, long sC) {
  A += (long)blockIdx.z * sA;
  B += (long)blockIdx.z * sB;
  Cc += (long)blockIdx.z * sC;

  __shared__ float As[2][8][128];
  __shared__ float Bs[2][8][132];
  const int bm = blockIdx.y * 128;
  const int bn = blockIdx.x * 128;
  const int tid = threadIdx.x;
  const int tx = tid & 15, ty = tid >> 4;
  const int arow = tid >> 1, acol = (tid & 1) * 4;
  const int brow = tid >> 5, bcol = (tid & 31) * 4;

  const float* Aptr = A + (size_t)(bm + arow) * lda + acol;
  const float* Bptr = B + (size_t)brow * ldb + bn + bcol;

  float acc[8][8];
#pragma unroll
  for (int i = 0; i < 8; i++)
#pragma unroll
    for (int j = 0; j < 8; j++) acc[i][j] = 0.f;

  {
    float4 av = *reinterpret_cast<const float4*>(Aptr);
    float4 bv = *reinterpret_cast<const float4*>(Bptr);
    As[0][acol + 0][arow] = av.x;
    As[0][acol + 1][arow] = av.y;
    As[0][acol + 2][arow] = av.z;
    As[0][acol + 3][arow] = av.w;
    Bs[0][brow][bcol + 0] = bv.x;
    Bs[0][brow][bcol + 1] = bv.y;
    Bs[0][brow][bcol + 2] = bv.z;
    Bs[0][brow][bcol + 3] = bv.w;
  }
  __syncthreads();

  int buf = 0;
  for (int k0 = 0; k0 < K; k0 += 8) {
    float4 av, bv;
    const bool more = (k0 + 8 < K);
    if (more) {
      av = *reinterpret_cast<const float4*>(Aptr + k0 + 8);
      bv = *reinterpret_cast<const float4*>(Bptr + (size_t)(k0 + 8) * ldb);
    }
#pragma unroll
    for (int kk = 0; kk < 8; kk++) {
      float a[8], b[8];
#pragma unroll
      for (int i = 0; i < 8; i++) a[i] = As[buf][kk][ty * 8 + i];
#pragma unroll
      for (int j = 0; j < 8; j++) b[j] = Bs[buf][kk][tx * 8 + j];
#pragma unroll
      for (int i = 0; i < 8; i++)
#pragma unroll
        for (int j = 0; j < 8; j++) acc[i][j] += a[i] * b[j];
    }
    if (more) {
      int nb = buf ^ 1;
      As[nb][acol + 0][arow] = av.x;
      As[nb][acol + 1][arow] = av.y;
      As[nb][acol + 2][arow] = av.z;
      As[nb][acol + 3][arow] = av.w;
      Bs[nb][brow][bcol + 0] = bv.x;
      Bs[nb][brow][bcol + 1] = bv.y;
      Bs[nb][brow][bcol + 2] = bv.z;
      Bs[nb][brow][bcol + 3] = bv.w;
      __syncthreads();
      buf = nb;
    }
  }

#pragma unroll
  for (int i = 0; i < 8; i++) {
    float* crow = Cc + (size_t)(bm + ty * 8 + i) * ldc + bn + tx * 8;
    *reinterpret_cast<float4*>(crow) = make_float4(acc[i][0], acc[i][1], acc[i][2], acc[i][3]);
    *reinterpret_cast<float4*>(crow + 4) = make_float4(acc[i][4], acc[i][5], acc[i][6], acc[i][7]);
  }
}

// ========== fused narrow projections: 5 independent (A @ B[2048x64]) ====
struct ProjArgs {
  const float* A[5];
  const float* B[5];
  float* Cc[5];
  int M[5];
};

__global__ __launch_bounds__(256, 2) void proj64_kernel(ProjArgs pa) {
  const int mat = blockIdx.x;
  const int bm = blockIdx.y * 128;
  if (bm >= pa.M[mat]) return;
  const float* A = pa.A[mat];
  const float* B = pa.B[mat];
  float* Cc = pa.Cc[mat];

  __shared__ float As[8][128];
  __shared__ float Bs[8][68];
  const int tid = threadIdx.x;
  const int tx = tid & 15, ty = tid >> 4;
  const int arow = tid >> 1, acol = (tid & 1) * 4;
  const int brow = tid >> 4, bcol = (tid & 15) * 4;
  const bool bload = (tid < 128);

  const float* Aptr = A + (size_t)(bm + arow) * D_DIM + acol;
  const float* Bptr = B + (size_t)brow * C_DIM + bcol;

  float acc[8][4];
#pragma unroll
  for (int i = 0; i < 8; i++)
#pragma unroll
    for (int j = 0; j < 4; j++) acc[i][j] = 0.f;

  float4 av = *reinterpret_cast<const float4*>(Aptr);
  float4 bv = bload ? *reinterpret_cast<const float4*>(Bptr) : make_float4(0, 0, 0, 0);

  for (int k0 = 0; k0 < D_DIM; k0 += 8) {
    As[acol + 0][arow] = av.x;
    As[acol + 1][arow] = av.y;
    As[acol + 2][arow] = av.z;
    As[acol + 3][arow] = av.w;
    if (bload) {
      Bs[brow][bcol + 0] = bv.x;
      Bs[brow][bcol + 1] = bv.y;
      Bs[brow][bcol + 2] = bv.z;
      Bs[brow][bcol + 3] = bv.w;
    }
    __syncthreads();

    if (k0 + 8 < D_DIM) {
      av = *reinterpret_cast<const float4*>(Aptr + k0 + 8);
      if (bload) bv = *reinterpret_cast<const float4*>(Bptr + (size_t)(k0 + 8) * C_DIM);
    }

#pragma unroll
    for (int kk = 0; kk < 8; kk++) {
      float a[8], b[4];
#pragma unroll
      for (int i = 0; i < 8; i++) a[i] = As[kk][ty * 8 + i];
#pragma unroll
      for (int j = 0; j < 4; j++) b[j] = Bs[kk][tx * 4 + j];
#pragma unroll
      for (int i = 0; i < 8; i++)
#pragma unroll
        for (int j = 0; j < 4; j++) acc[i][j] += a[i] * b[j];
    }
    __syncthreads();
  }

#pragma unroll
  for (int i = 0; i < 8; i++) {
    float* crow = Cc + (size_t)(bm + ty * 8 + i) * C_DIM + tx * 4;
    *reinterpret_cast<float4*>(crow) = make_float4(acc[i][0], acc[i][1], acc[i][2], acc[i][3]);
  }
}

// ========== hw = x @ w_w [2048x4]: one warp per row ====================
__global__ void hw_kernel(const float* __restrict__ x, const float* __restrict__ w_w) {
  int warp = (blockIdx.x * blockDim.x + threadIdx.x) >> 5;
  int lane = threadIdx.x & 31;
  if (warp >= S_LEN) return;
  const float4* xr = reinterpret_cast<const float4*>(x + (size_t)warp * D_DIM);
  const float4* wr = reinterpret_cast<const float4*>(w_w);
  float d0 = 0.f, d1 = 0.f, d2 = 0.f, d3 = 0.f;
  for (int i = lane; i < D_DIM / 4; i += 32) {
    float4 xv = xr[i];
    float4 w0 = wr[i * 4 + 0];
    float4 w1 = wr[i * 4 + 1];
    float4 w2 = wr[i * 4 + 2];
    float4 w3 = wr[i * 4 + 3];
    d0 += xv.x * w0.x + xv.y * w1.x + xv.z * w2.x + xv.w * w3.x;
    d1 += xv.x * w0.y + xv.y * w1.y + xv.z * w2.y + xv.w * w3.y;
    d2 += xv.x * w0.z + xv.y * w1.z + xv.z * w2.z + xv.w * w3.z;
    d3 += xv.x * w0.w + xv.y * w1.w + xv.z * w2.w + xv.w * w3.w;
  }
#pragma unroll
  for (int off = 16; off > 0; off >>= 1) {
    d0 += __shfl_down_sync(0xffffffffu, d0, off);
    d1 += __shfl_down_sync(0xffffffffu, d1, off);
    d2 += __shfl_down_sync(0xffffffffu, d2, off);
    d3 += __shfl_down_sync(0xffffffffu, d3, off);
  }
  if (lane == 0) {
    g_hw[warp * 4 + 0] = d0;
    g_hw[warp * 4 + 1] = d1;
    g_hw[warp * 4 + 2] = d2;
    g_hw[warp * 4 + 3] = d3;
  }
}

// ---------------- k_orig = mean over the M=4 tokens of each chunk -------
__global__ void kmean_kernel(const float* __restrict__ x) {
  int idx = blockIdx.x * 256 + threadIdx.x;
  if (idx >= NC_CH * D_DIM) return;
  int nc = idx / D_DIM, d = idx - nc * D_DIM;
  const float* p = x + (size_t)nc * 4 * D_DIM + d;
  g_ko[idx] = 0.25f * (p[0] + p[D_DIM] + p[2 * D_DIM] + p[3 * D_DIM]);
}

// ------------- compression softmax (over 8 candidates) + LayerNorm ------
__global__ void compress_kernel(const float* __restrict__ b_a,
                                const float* __restrict__ b_b,
                                const float* __restrict__ kvn_w,
                                const float* __restrict__ kvn_b) {
  int nc = blockIdx.x;
  int c = threadIdx.x;  // 64
  float lg[8], val[8];
#pragma unroll
  for (int m = 0; m < 4; m++) {
    int cur = (nc * 4 + m) * 64 + c;
    lg[4 + m] = g_za[cur] + b_a[m * 64 + c];
    val[4 + m] = g_ca[cur];
    if (nc > 0) {
      int prev = ((nc - 1) * 4 + m) * 64 + c;
      lg[m] = g_zb[prev] + b_b[m * 64 + c];
      val[m] = g_cb[prev];
    } else {
      lg[m] = -1e30f + b_b[m * 64 + c];
      val[m] = 0.f;
    }
  }
  float mx = lg[0];
#pragma unroll
  for (int i = 1; i < 8; i++) mx = fmaxf(mx, lg[i]);
  float se = 0.f, comp = 0.f;
#pragma unroll
  for (int i = 0; i < 8; i++) {
    float e = expf(lg[i] - mx);
    se += e;
    comp += e * val[i];
  }
  comp /= se;

  __shared__ float red[64];
  red[c] = comp;
  __syncthreads();
  for (int off = 32; off > 0; off >>= 1) {
    if (c < off) red[c] += red[c + off];
    __syncthreads();
  }
  float mu = red[0] * (1.f / 64.f);
  __syncthreads();
  float dv = comp - mu;
  red[c] = dv * dv;
  __syncthreads();
  for (int off = 32; off > 0; off >>= 1) {
    if (c < off) red[c] += red[c + off];
    __syncthreads();
  }
  float var = red[0] * (1.f / 64.f);
  g_kc[nc * 64 + c] = dv * rsqrtf(var + 1e-6f) * kvn_w[c] + kvn_b[c];
}

// ------------- per-(s,h) LayerNorm then RoPE on last 32 channels --------
__global__ void qln_rope_kernel(const float* __restrict__ qn_w,
                                const float* __restrict__ qn_b) {
  int s = blockIdx.x;
  int c = threadIdx.x;  // 64
  int h = threadIdx.y;  // 16
  float v = g_qf[(size_t)s * 1024 + h * 64 + c];
  __shared__ float red[16][64];
  __shared__ float lnb[16][65];
  red[h][c] = v;
  __syncthreads();
  for (int off = 32; off > 0; off >>= 1) {
    if (c < off) red[h][c] += red[h][c + off];
    __syncthreads();
  }
  float mu = red[h][0] * (1.f / 64.f);
  __syncthreads();
  float dv = v - mu;
  red[h][c] = dv * dv;
  __syncthreads();
  for (int off = 32; off > 0; off >>= 1) {
    if (c < off) red[h][c] += red[h][c + off];
    __syncthreads();
  }
  float var = red[h][0] * (1.f / 64.f);
  float ln = dv * rsqrtf(var + 1e-6f) * qn_w[c] + qn_b[c];
  lnb[h][c] = ln;
  __syncthreads();
  float outv;
  if (c < 32) {
    outv = ln;
  } else {
    int j = (c - 32) >> 1;
    float inv = exp2f(-(float)j * 0.830482023722f);  // 10000^(-j/16)
    float ang = (float)s * inv;
    float cs = cosf(ang), sn = sinf(ang);
    float x0 = lnb[h][32 + 2 * j], x1 = lnb[h][32 + 2 * j + 1];
    outv = ((c & 1) == 0) ? (x0 * cs - x1 * sn) : (x0 * sn + x1 * cs);
  }
  g_qf[(size_t)s * 1024 + h * 64 + c] = outv;
}

// ------------- indexer scores: relu(q_i . k_proj) weighted by hw --------
__global__ void iscore_kernel() {
  int s = blockIdx.x;
  __shared__ float qs[256];
  __shared__ float ws[4];
  int tid = threadIdx.x;  // 256
  qs[tid] = g_qi[(size_t)s * 256 + tid];
  if (tid < 4) ws[tid] = g_hw[s * 4 + tid];
  __syncthreads();
  const float4* qs4 = reinterpret_cast<const float4*>(qs);
  for (int k = tid; k < NC_CH; k += 256) {
    const float4* kr = reinterpret_cast<const float4*>(g_kp + k * 64);
    float d0 = 0.f, d1 = 0.f, d2 = 0.f, d3 = 0.f;
#pragma unroll
    for (int c4 = 0; c4 < 16; c4++) {
      float4 kv = kr[c4];
      float4 q0 = qs4[c4];
      float4 q1 = qs4[16 + c4];
      float4 q2 = qs4[32 + c4];
      float4 q3 = qs4[48 + c4];
      d0 += q0.x * kv.x + q0.y * kv.y + q0.z * kv.z + q0.w * kv.w;
      d1 += q1.x * kv.x + q1.y * kv.y + q1.z * kv.z + q1.w * kv.w;
      d2 += q2.x * kv.x + q2.y * kv.y + q2.z * kv.z + q2.w * kv.w;
      d3 += q3.x * kv.x + q3.y * kv.y + q3.z * kv.z + q3.w * kv.w;
    }
    float sc = fmaxf(d0, 0.f) * ws[0] + fmaxf(d1, 0.f) * ws[1] +
               fmaxf(d2, 0.f) * ws[2] + fmaxf(d3, 0.f) * ws[3];
    g_is[(size_t)s * NC_CH + k] = (k < s) ? sc : NEG_INF;
  }
}

// ------------- exact top-512: bitonic sort by (value desc, index asc) ---
__global__ __launch_bounds__(512) void topk_kernel() {
  int s = blockIdx.x, tid = threadIdx.x;  // 512
  __shared__ float v[1024];
  __shared__ int ix[1024];
  v[tid] = g_is[(size_t)s * 1024 + tid];
  ix[tid] = tid;
  v[tid + 512] = g_is[(size_t)s * 1024 + tid + 512];
  ix[tid + 512] = tid + 512;
  __syncthreads();
  for (int k = 2; k <= 1024; k <<= 1) {
    for (int j = k >> 1; j > 0; j >>= 1) {
      for (int t = tid; t < 1024; t += 512) {
        int p = t ^ j;
        if (p > t) {
          float va = v[t], vb = v[p];
          int ia = ix[t], ib = ix[p];
          bool before = (va > vb) || (va == vb && ia < ib);
          bool dir = ((t & k) == 0);
          if (before != dir) {
            v[t] = vb; v[p] = va;
            ix[t] = ib; ix[p] = ia;
          }
        }
      }
      __syncthreads();
    }
  }
  g_ti[(size_t)s * 512 + tid] = ix[tid];
}

// ------------- gathered sparse attention (4 quarters of 128 chunks) -----
// smem: qs 4KB + Ks 34KB + ew 8KB + denom = ~47.2KB (under 48KB static).
__global__ __launch_bounds__(256) void attn_kernel(const float* __restrict__ sink) {
  const int s = blockIdx.x, tid = threadIdx.x;  // 256
  __shared__ float qs[1024];
  __shared__ float Ks[128][68];
  __shared__ float ew[16][128];
  __shared__ float denom[16];

#pragma unroll
  for (int i = 0; i < 4; i++) qs[tid + 256 * i] = g_qf[(size_t)s * 1024 + tid + 256 * i];
  if (tid < 16) denom[tid] = __expf(sink[tid]);
  __syncthreads();

  const int c = tid & 63, g = tid >> 6;
  float acc0 = 0.f, acc1 = 0.f, acc2 = 0.f, acc3 = 0.f;
  const float4* qs4 = reinterpret_cast<const float4*>(qs);
  const int* trow = g_ti + (size_t)s * 512;

  for (int qtr = 0; qtr < 4; qtr++) {
    if (qtr) __syncthreads();  // all phase-3 reads of Ks/ew done before restage

    // stage 128 gathered K rows: 2 threads per row, 8 float4 each
    {
      int j = tid >> 1, p = tid & 1;
      int ck = trow[qtr * 128 + j];
      const float4* src = reinterpret_cast<const float4*>(g_kc + ck * 64);
      float4* dst = reinterpret_cast<float4*>(&Ks[j][0]);
#pragma unroll
      for (int q = 0; q < 8; q++) dst[p + 2 * q] = src[p + 2 * q];
    }
    __syncthreads();

    // phase 1: scores -> exp; 2 threads per chunk, 8 heads each
    {
      int kk = tid >> 1, hh = (tid & 1) * 8;
      int ck = trow[qtr * 128 + kk];
      bool valid = (s < ck * 4);
      const float4* kr = reinterpret_cast<const float4*>(&Ks[kk][0]);
      float d[8];
#pragma unroll
      for (int h = 0; h < 8; h++) d[h] = 0.f;
#pragma unroll
      for (int c4 = 0; c4 < 16; c4++) {
        float4 kv = kr[c4];
#pragma unroll
        for (int h = 0; h < 8; h++) {
          float4 qv = qs4[(hh + h) * 16 + c4];
          d[h] += qv.x * kv.x + qv.y * kv.y + qv.z * kv.z + qv.w * kv.w;
        }
      }
#pragma unroll
      for (int h = 0; h < 8; h++) ew[hh + h][kk] = valid ? __expf(d[h] * 0.125f) : 0.f;
    }
    __syncthreads();

    // phase 2: denominators via shuffle (h = tid>>4, 16 lanes per h)
    {
      int h = tid >> 4, seg = tid & 15;
      float p = 0.f;
#pragma unroll
      for (int k = 0; k < 8; k++) p += ew[h][seg * 8 + k];
#pragma unroll
      for (int off = 8; off > 0; off >>= 1) p += __shfl_down_sync(0xffffffffu, p, off);
      if (seg == 0) denom[h] += p;
    }

    // phase 3: AV accumulation from smem
    for (int k = 0; k < 128; k++) {
      float kv = Ks[k][c];
      acc0 += ew[g][k] * kv;
      acc1 += ew[g + 4][k] * kv;
      acc2 += ew[g + 8][k] * kv;
      acc3 += ew[g + 12][k] * kv;
    }
  }
  __syncthreads();  // denom writes visible

  g_ao[(size_t)s * 1024 + (g) * 64 + c] = acc0 / denom[g];
  g_ao[(size_t)s * 1024 + (g + 4) * 64 + c] = acc1 / denom[g + 4];
  g_ao[(size_t)s * 1024 + (g + 8) * 64 + c] = acc2 / denom[g + 8];
  g_ao[(size_t)s * 1024 + (g + 12) * 64 + c] = acc3 / denom[g + 12];
}

// ---------------------------- launcher ----------------------------------
extern "C" void kernel_launch(void* const* d_in, const int* in_sizes, int n_in,
                              void* d_out, int out_size) {
  (void)in_sizes; (void)n_in; (void)out_size;
  const float* x      = (const float*)d_in[0];
  const float* w_kva  = (const float*)d_in[1];
  const float* w_kvb  = (const float*)d_in[2];
  const float* w_za   = (const float*)d_in[3];
  const float* w_zb   = (const float*)d_in[4];
  const float* b_a    = (const float*)d_in[5];
  const float* b_b    = (const float*)d_in[6];
  const float* w_dq   = (const float*)d_in[7];
  const float* w_iuq  = (const float*)d_in[8];
  const float* w_w    = (const float*)d_in[9];
  const float* w_k    = (const float*)d_in[10];
  const float* w_uq   = (const float*)d_in[11];
  const float* o_down = (const float*)d_in[12];
  const float* o_up   = (const float*)d_in[13];
  const float* kvn_w  = (const float*)d_in[14];
  const float* kvn_b  = (const float*)d_in[15];
  const float* qn_w   = (const float*)d_in[16];
  const float* qn_b   = (const float*)d_in[17];
  const float* sink   = (const float*)d_in[18];
  float* out = (float*)d_out;

  void *p_ca, *p_cb, *p_za, *p_zb, *p_cq, *p_qi, *p_ko, *p_kp, *p_qf, *p_ao, *p_gb;
  cudaGetSymbolAddress(&p_ca, g_ca);
  cudaGetSymbolAddress(&p_cb, g_cb);
  cudaGetSymbolAddress(&p_za, g_za);
  cudaGetSymbolAddress(&p_zb, g_zb);
  cudaGetSymbolAddress(&p_cq, g_cq);
  cudaGetSymbolAddress(&p_qi, g_qi);
  cudaGetSymbolAddress(&p_ko, g_ko);
  cudaGetSymbolAddress(&p_kp, g_kp);
  cudaGetSymbolAddress(&p_qf, g_qf);
  cudaGetSymbolAddress(&p_ao, g_ao);
  cudaGetSymbolAddress(&p_gb, g_gb);

  auto grid2 = [](int M, int N) { return dim3((unsigned)(N / 128), (unsigned)(M / 128), 1u); };

  // chunk means first (feeds k_proj inside fused projections)
  kmean_kernel<<<(NC_CH * D_DIM + 255) / 256, 256>>>(x);

  // fused narrow projections
  ProjArgs pa;
  pa.A[0] = x;     pa.B[0] = w_kva; pa.Cc[0] = (float*)p_ca; pa.M[0] = S_LEN;
  pa.A[1] = x;     pa.B[1] = w_kvb; pa.Cc[1] = (float*)p_cb; pa.M[1] = S_LEN;
  pa.A[2] = x;     pa.B[2] = w_za;  pa.Cc[2] = (float*)p_za; pa.M[2] = S_LEN;
  pa.A[3] = x;     pa.B[3] = w_zb;  pa.Cc[3] = (float*)p_zb; pa.M[3] = S_LEN;
  pa.A[4] = (const float*)p_ko; pa.B[4] = w_k; pa.Cc[4] = (float*)p_kp; pa.M[4] = NC_CH;
  proj64_kernel<<<dim3(5, S_LEN / 128), 256>>>(pa);

  // hw = x @ w_w
  hw_kernel<<<S_LEN / 8, 256>>>(x, w_w);

  // c_q = x @ w_dq
  sgemm_kernel<<<grid2(S_LEN, DC_N), 256>>>(x, w_dq, (float*)p_cq, D_DIM, D_DIM, DC_N, DC_N, 0, 0, 0);

  // chunk compression + LN(kc)
  compress_kernel<<<NC_CH, 64>>>(b_a, b_b, kvn_w, kvn_b);

  // indexer path
  sgemm_kernel<<<grid2(S_LEN, NHI_N * CI_N), 256>>>((const float*)p_cq, w_iuq, (float*)p_qi,
                                                    DC_N, DC_N, NHI_N * CI_N, NHI_N * CI_N, 0, 0, 0);
  iscore_kernel<<<S_LEN, 256>>>();
  topk_kernel<<<S_LEN, 512>>>();

  // q path (LN + rope in-place)
  sgemm_kernel<<<grid2(S_LEN, NH_N * C_DIM), 256>>>((const float*)p_cq, w_uq, (float*)p_qf,
                                                    DC_N, DC_N, NH_N * C_DIM, NH_N * C_DIM, 0, 0, 0);
  qln_rope_kernel<<<S_LEN, dim3(64, 16)>>>(qn_w, qn_b);

  // sparse attention over top-k compressed chunks
  attn_kernel<<<S_LEN, 256>>>(sink);

  // grouped o_down: ONE batched launch (z = group)
  sgemm_kernel<<<dim3(DG_N / 128, S_LEN / 128, NG_N), 256>>>(
      (const float*)p_ao, o_down, (float*)p_gb,
      256, NH_N * C_DIM, DG_N, NG_N * DG_N,
      /*sA=*/256, /*sB=*/(long)256 * DG_N, /*sC=*/DG_N);

  // o_up
  sgemm_kernel<<<grid2(S_LEN, D_DIM), 256>>>((const float*)p_gb, o_up, out,
                                             NG_N * DG_N, NG_N * DG_N, D_DIM, D_DIM, 0, 0, 0);
}